// round 4
// baseline (speedup 1.0000x reference)
#include <cuda_runtime.h>
#include <cstdint>

#define NN 50000
#define NE 640000
#define EMB 128
#define SCAN_BLOCKS 196   // 196*256 = 50176 >= NN
#define NB_TILE 391       // (NN+127)/128

// ---- scratch (device globals; zero-initialized at load, re-zeroed each launch) ----
__device__ float g_hA[NN * EMB];      // 25.6 MB
__device__ float g_hB[NN * EMB];      // 25.6 MB
__device__ float g_norm_src[NN];
__device__ float g_norm_dst[NN];
__device__ int   g_deg_src[NN];       // zeroed at end of scanB each launch
__device__ int   g_deg_dst[NN];
__device__ int   g_row_ptr[NN + 1];
__device__ int   g_cursor[NN];
__device__ int   g_col[NE];
__device__ float g_colw[NE];
__device__ int   g_part[SCAN_BLOCKS];

// ---------------------------------------------------------------
__global__ void k_count(const int* __restrict__ src, const int* __restrict__ dst) {
    int e = blockIdx.x * blockDim.x + threadIdx.x;
    if (e < NE) {
        atomicAdd(&g_deg_src[src[e]], 1);
        atomicAdd(&g_deg_dst[dst[e]], 1);
    }
}

__global__ void k_scanA() {
    __shared__ int sh[256];
    int i = blockIdx.x * 256 + threadIdx.x;
    int d = (i < NN) ? g_deg_dst[i] : 0;
    sh[threadIdx.x] = d;
    __syncthreads();
    #pragma unroll
    for (int off = 128; off; off >>= 1) {
        if (threadIdx.x < off) sh[threadIdx.x] += sh[threadIdx.x + off];
        __syncthreads();
    }
    if (threadIdx.x == 0) g_part[blockIdx.x] = sh[0];
}

__global__ void k_scanB() {
    __shared__ int sh[256];
    __shared__ int pre;
    int tid = threadIdx.x;
    int b = blockIdx.x;
    int pv = (tid < b) ? g_part[tid] : 0;
    sh[tid] = pv;
    __syncthreads();
    #pragma unroll
    for (int off = 128; off; off >>= 1) {
        if (tid < off) sh[tid] += sh[tid + off];
        __syncthreads();
    }
    if (tid == 0) pre = sh[0];
    __syncthreads();
    int prefix = pre;
    __syncthreads();

    int i = b * 256 + tid;
    int d = (i < NN) ? g_deg_dst[i] : 0;
    sh[tid] = d;
    __syncthreads();
    #pragma unroll
    for (int off = 1; off < 256; off <<= 1) {
        int v = (tid >= off) ? sh[tid - off] : 0;
        __syncthreads();
        sh[tid] += v;
        __syncthreads();
    }
    int incl = sh[tid];
    int excl = incl - d;
    if (i < NN) {
        int base = prefix + excl;
        g_row_ptr[i] = base;
        g_cursor[i]  = base;
        if (i == NN - 1) g_row_ptr[NN] = prefix + incl;
        int ds = g_deg_src[i];
        g_norm_dst[i] = rsqrtf((float)max(d, 1));
        g_norm_src[i] = rsqrtf((float)max(ds, 1));
        g_deg_dst[i] = 0;
        g_deg_src[i] = 0;
    }
}

__global__ void k_fill(const int* __restrict__ src, const int* __restrict__ dst) {
    int e = blockIdx.x * blockDim.x + threadIdx.x;
    if (e < NE) {
        int s = src[e];
        int pos = atomicAdd(&g_cursor[dst[e]], 1);
        g_col[pos]  = s;
        g_colw[pos] = g_norm_src[s];   // fold src-side norm into edge weight
    }
}

// ---------------------------------------------------------------
__device__ __forceinline__ uint32_t f2tf32(float f) {
    uint32_t r;
    asm("cvt.rna.tf32.f32 %0, %1;" : "=r"(r) : "f"(f));
    return r;
}

// GEMM core: accumulators from Su[m][k] (tf32, stride 132, full K=128)
// times W[128x128] (staged chunk-wise into Ws[32][132]).
// 8 warps (4x2), warp tile 32(m) x 64(n).
__device__ __forceinline__ void mma_phase(const uint32_t* Su, uint32_t* Ws,
                                          const float* __restrict__ W,
                                          float c[2][8][4]) {
    int tid = threadIdx.x;
    int warp = tid >> 5, lane = tid & 31;
    int wm = warp & 3, wn = warp >> 2;
    int lg = lane >> 2, lt = lane & 3;

    for (int kc = 0; kc < 4; kc++) {
        int k0 = kc * 32;
        #pragma unroll
        for (int it = 0; it < 4; it++) {
            int f = tid + it * 256;
            int k = f >> 5;
            int n = (f & 31) << 2;
            float4 w = *(const float4*)(W + (size_t)(k0 + k) * 128 + n);
            Ws[k * 132 + n + 0] = f2tf32(w.x);
            Ws[k * 132 + n + 1] = f2tf32(w.y);
            Ws[k * 132 + n + 2] = f2tf32(w.z);
            Ws[k * 132 + n + 3] = f2tf32(w.w);
        }
        __syncthreads();

        #pragma unroll
        for (int ks = 0; ks < 32; ks += 8) {
            uint32_t af[2][4];
            #pragma unroll
            for (int mt = 0; mt < 2; mt++) {
                int m = wm * 32 + mt * 16 + lg;
                const uint32_t* r0 = Su + (size_t)m * 132 + k0 + ks;
                const uint32_t* r1 = Su + (size_t)(m + 8) * 132 + k0 + ks;
                af[mt][0] = r0[lt];
                af[mt][1] = r1[lt];
                af[mt][2] = r0[lt + 4];
                af[mt][3] = r1[lt + 4];
            }
            #pragma unroll
            for (int nt = 0; nt < 8; nt++) {
                int n = wn * 64 + nt * 8 + lg;
                uint32_t b0 = Ws[(ks + lt) * 132 + n];
                uint32_t b1 = Ws[(ks + 4 + lt) * 132 + n];
                #pragma unroll
                for (int mt = 0; mt < 2; mt++) {
                    asm volatile(
                        "mma.sync.aligned.m16n8k8.row.col.f32.tf32.tf32.f32 "
                        "{%0,%1,%2,%3}, {%4,%5,%6,%7}, {%8,%9}, {%0,%1,%2,%3};"
                        : "+f"(c[mt][nt][0]), "+f"(c[mt][nt][1]),
                          "+f"(c[mt][nt][2]), "+f"(c[mt][nt][3])
                        : "r"(af[mt][0]), "r"(af[mt][1]),
                          "r"(af[mt][2]), "r"(af[mt][3]),
                          "r"(b0), "r"(b1));
                }
            }
        }
        __syncthreads();
    }
}

// bias + relu + store
__device__ __forceinline__ void store_epilogue(float c[2][8][4],
                                               const float* __restrict__ bias,
                                               float* __restrict__ C,
                                               int row0, int M) {
    int tid = threadIdx.x;
    int warp = tid >> 5, lane = tid & 31;
    int wm = warp & 3, wn = warp >> 2;
    int lg = lane >> 2, lt = lane & 3;
    #pragma unroll
    for (int nt = 0; nt < 8; nt++) {
        int col = wn * 64 + nt * 8 + 2 * lt;
        float2 bv = *(const float2*)(bias + col);
        #pragma unroll
        for (int mt = 0; mt < 2; mt++) {
            int r = row0 + wm * 32 + mt * 16 + lg;
            float2 o0, o1;
            o0.x = fmaxf(c[mt][nt][0] + bv.x, 0.f);
            o0.y = fmaxf(c[mt][nt][1] + bv.y, 0.f);
            o1.x = fmaxf(c[mt][nt][2] + bv.x, 0.f);
            o1.y = fmaxf(c[mt][nt][3] + bv.y, 0.f);
            if (r < M)     *(float2*)(C + (size_t)r * 128 + col)       = o0;
            if (r + 8 < M) *(float2*)(C + (size_t)(r + 8) * 128 + col) = o1;
        }
    }
}

// ---------------------------------------------------------------
// Layer 1 fused: embed + spmm + gemm.
// agg128[dst] = (sum_e w*nf4[src]) @ W_emb + (sum_e w) * b_emb, then *norm_dst,
// then GEMM with Wg0 + bias + relu -> C.
// dyn smem: Su[128*132] u32 | Ws[32*132] u32 | We[512] f | be[128] f
__global__ void __launch_bounds__(256)
k_l1(const float* __restrict__ nf, const float* __restrict__ Wemb,
     const float* __restrict__ bemb, const float* __restrict__ W,
     const float* __restrict__ bias, float* __restrict__ C) {
    extern __shared__ char smem_raw[];
    uint32_t* Su = (uint32_t*)smem_raw;
    uint32_t* Ws = Su + 128 * 132;
    float* We = (float*)(Ws + 32 * 132);
    float* be = We + 512;

    int tid = threadIdx.x;
    int warp = tid >> 5, lane = tid & 31;
    int row0 = blockIdx.x * 128;

    if (tid < 256) {
        We[tid] = Wemb[tid];
        We[tid + 256] = Wemb[tid + 256];
        if (tid < 128) be[tid] = bemb[tid];
    }
    __syncthreads();

    // phase 1: gather 4-dim + expand to 128
    for (int mi = 0; mi < 16; mi++) {
        int m = warp * 16 + mi;
        int gr = row0 + m;
        float4 acc = make_float4(0.f, 0.f, 0.f, 0.f);
        float ws = 0.f;
        if (gr < NN) {
            int beg = g_row_ptr[gr];
            int end = g_row_ptr[gr + 1];
            for (int j = beg + lane; j < end; j += 32) {
                int s = __ldg(&g_col[j]);
                float w = __ldg(&g_colw[j]);
                float4 v = *(const float4*)(nf + (size_t)s * 4);
                acc.x += w * v.x; acc.y += w * v.y;
                acc.z += w * v.z; acc.w += w * v.w;
                ws += w;
            }
        }
        #pragma unroll
        for (int o = 16; o; o >>= 1) {
            acc.x += __shfl_xor_sync(0xffffffffu, acc.x, o);
            acc.y += __shfl_xor_sync(0xffffffffu, acc.y, o);
            acc.z += __shfl_xor_sync(0xffffffffu, acc.z, o);
            acc.w += __shfl_xor_sync(0xffffffffu, acc.w, o);
            ws    += __shfl_xor_sync(0xffffffffu, ws, o);
        }
        float nd = (gr < NN) ? g_norm_dst[gr] : 0.f;
        #pragma unroll
        for (int q = 0; q < 4; q++) {
            int k = lane * 4 + q;
            float s = acc.x * We[k] + acc.y * We[128 + k] +
                      acc.z * We[256 + k] + acc.w * We[384 + k] + ws * be[k];
            Su[(size_t)m * 132 + k] = f2tf32(s * nd);
        }
    }
    __syncthreads();

    float c[2][8][4] = {};
    mma_phase(Su, Ws, W, c);
    store_epilogue(c, bias, C, row0, NN);
}

// ---------------------------------------------------------------
// Layers 2/3 fused: spmm + gemm.  reads h (prev layer), writes C.
// dyn smem: Su[128*132] u32 | Ws[32*132] u32
__global__ void __launch_bounds__(256)
k_spmm_gemm(const float* __restrict__ h, const float* __restrict__ W,
            const float* __restrict__ bias, float* __restrict__ C) {
    extern __shared__ char smem_raw[];
    uint32_t* Su = (uint32_t*)smem_raw;
    uint32_t* Ws = Su + 128 * 132;

    int tid = threadIdx.x;
    int warp = tid >> 5, lane = tid & 31;
    int row0 = blockIdx.x * 128;

    // phase 1: 128-dim gather, lane owns cols lane*4..+3
    for (int mi = 0; mi < 16; mi++) {
        int m = warp * 16 + mi;
        int gr = row0 + m;
        float4 acc = make_float4(0.f, 0.f, 0.f, 0.f);
        if (gr < NN) {
            int beg = g_row_ptr[gr];
            int end = g_row_ptr[gr + 1];
            int j = beg;
            for (; j + 2 <= end; j += 2) {
                int   s0 = __ldg(&g_col[j]);
                int   s1 = __ldg(&g_col[j + 1]);
                float w0 = __ldg(&g_colw[j]);
                float w1 = __ldg(&g_colw[j + 1]);
                float4 v0 = *(const float4*)(h + (size_t)s0 * EMB + lane * 4);
                float4 v1 = *(const float4*)(h + (size_t)s1 * EMB + lane * 4);
                acc.x += w0 * v0.x + w1 * v1.x;
                acc.y += w0 * v0.y + w1 * v1.y;
                acc.z += w0 * v0.z + w1 * v1.z;
                acc.w += w0 * v0.w + w1 * v1.w;
            }
            if (j < end) {
                int   s0 = __ldg(&g_col[j]);
                float w0 = __ldg(&g_colw[j]);
                float4 v0 = *(const float4*)(h + (size_t)s0 * EMB + lane * 4);
                acc.x += w0 * v0.x; acc.y += w0 * v0.y;
                acc.z += w0 * v0.z; acc.w += w0 * v0.w;
            }
            float nd = g_norm_dst[gr];
            acc.x *= nd; acc.y *= nd; acc.z *= nd; acc.w *= nd;
        }
        uint32_t* row = Su + (size_t)m * 132 + lane * 4;
        row[0] = f2tf32(acc.x);
        row[1] = f2tf32(acc.y);
        row[2] = f2tf32(acc.z);
        row[3] = f2tf32(acc.w);
    }
    __syncthreads();

    float c[2][8][4] = {};
    mma_phase(Su, Ws, W, c);
    store_epilogue(c, bias, C, row0, NN);
}

// ---------------------------------------------------------------
// Final fused: out[r] = relu(A[r,:] @ Wo1 + b1) . w2 + b2
// A staged from global chunk-wise (As[k][m] like round 3), gemv in epilogue.
__global__ void __launch_bounds__(256)
k_gemm_gemv(const float* __restrict__ A, const float* __restrict__ W,
            const float* __restrict__ bias, const float* __restrict__ w2,
            const float* __restrict__ b2, float* __restrict__ out, int M) {
    __shared__ uint32_t As[32][132];
    __shared__ uint32_t Ws[32][132];
    __shared__ float red[128];
    __shared__ float w2s[128];
    int tid  = threadIdx.x;
    int warp = tid >> 5, lane = tid & 31;
    int wm = warp & 3, wn = warp >> 2;
    int lg = lane >> 2, lt = lane & 3;
    int row0 = blockIdx.x * 128;

    if (tid < 128) { red[tid] = 0.f; w2s[tid] = w2[tid]; }

    float c[2][8][4] = {};

    for (int k0 = 0; k0 < 128; k0 += 32) {
        #pragma unroll
        for (int it = 0; it < 4; it++) {
            int f  = tid + it * 256;
            int m  = f >> 3;
            int kq = (f & 7) << 2;
            int gr = row0 + m;
            float4 a = (gr < M) ? *(const float4*)(A + (size_t)gr * 128 + k0 + kq)
                                : make_float4(0.f, 0.f, 0.f, 0.f);
            As[kq + 0][m] = f2tf32(a.x);
            As[kq + 1][m] = f2tf32(a.y);
            As[kq + 2][m] = f2tf32(a.z);
            As[kq + 3][m] = f2tf32(a.w);
        }
        #pragma unroll
        for (int it = 0; it < 4; it++) {
            int f = tid + it * 256;
            int k = f >> 5;
            int n = (f & 31) << 2;
            float4 w = *(const float4*)(W + (size_t)(k0 + k) * 128 + n);
            Ws[k][n + 0] = f2tf32(w.x);
            Ws[k][n + 1] = f2tf32(w.y);
            Ws[k][n + 2] = f2tf32(w.z);
            Ws[k][n + 3] = f2tf32(w.w);
        }
        __syncthreads();

        #pragma unroll
        for (int ks = 0; ks < 32; ks += 8) {
            uint32_t af[2][4];
            #pragma unroll
            for (int mt = 0; mt < 2; mt++) {
                int m = wm * 32 + mt * 16 + lg;
                af[mt][0] = As[ks + lt][m];
                af[mt][1] = As[ks + lt][m + 8];
                af[mt][2] = As[ks + 4 + lt][m];
                af[mt][3] = As[ks + 4 + lt][m + 8];
            }
            #pragma unroll
            for (int nt = 0; nt < 8; nt++) {
                int n = wn * 64 + nt * 8 + lg;
                uint32_t b0 = Ws[ks + lt][n];
                uint32_t b1 = Ws[ks + 4 + lt][n];
                #pragma unroll
                for (int mt = 0; mt < 2; mt++) {
                    asm volatile(
                        "mma.sync.aligned.m16n8k8.row.col.f32.tf32.tf32.f32 "
                        "{%0,%1,%2,%3}, {%4,%5,%6,%7}, {%8,%9}, {%0,%1,%2,%3};"
                        : "+f"(c[mt][nt][0]), "+f"(c[mt][nt][1]),
                          "+f"(c[mt][nt][2]), "+f"(c[mt][nt][3])
                        : "r"(af[mt][0]), "r"(af[mt][1]),
                          "r"(af[mt][2]), "r"(af[mt][3]),
                          "r"(b0), "r"(b1));
                }
            }
        }
        __syncthreads();
    }

    // epilogue: relu(c+bias) . w2  -> shared reduce -> out
    #pragma unroll
    for (int mt = 0; mt < 2; mt++) {
        float dot0 = 0.f, dot1 = 0.f;
        #pragma unroll
        for (int nt = 0; nt < 8; nt++) {
            int col = wn * 64 + nt * 8 + 2 * lt;
            float2 bv = *(const float2*)(bias + col);
            float wa = w2s[col], wb = w2s[col + 1];
            dot0 += fmaxf(c[mt][nt][0] + bv.x, 0.f) * wa
                  + fmaxf(c[mt][nt][1] + bv.y, 0.f) * wb;
            dot1 += fmaxf(c[mt][nt][2] + bv.x, 0.f) * wa
                  + fmaxf(c[mt][nt][3] + bv.y, 0.f) * wb;
        }
        int rl = wm * 32 + mt * 16 + lg;
        atomicAdd(&red[rl], dot0);
        atomicAdd(&red[rl + 8], dot1);
    }
    __syncthreads();
    if (tid < 128 && row0 + tid < M)
        out[row0 + tid] = red[tid] + b2[0];
}

// ---------------------------------------------------------------
extern "C" void kernel_launch(void* const* d_in, const int* in_sizes, int n_in,
                              void* d_out, int out_size) {
    const float* nf   = (const float*)d_in[0];
    const int*   src  = (const int*)d_in[1];
    const int*   dst  = (const int*)d_in[2];
    const float* Wemb = (const float*)d_in[3];
    const float* bemb = (const float*)d_in[4];
    const float* Wg   = (const float*)d_in[5];
    const float* bg   = (const float*)d_in[6];
    const float* Wo1  = (const float*)d_in[7];
    const float* bo1  = (const float*)d_in[8];
    const float* Wo2  = (const float*)d_in[9];
    const float* bo2  = (const float*)d_in[10];
    float* out = (float*)d_out;

    float *hA, *hB;
    cudaGetSymbolAddress((void**)&hA, g_hA);
    cudaGetSymbolAddress((void**)&hB, g_hB);

    const int SM_FUSED = (128 * 132 + 32 * 132) * 4;          // 84480
    const int SM_L1    = SM_FUSED + (512 + 128) * 4;          // 87040
    cudaFuncSetAttribute(k_l1, cudaFuncAttributeMaxDynamicSharedMemorySize, SM_L1);
    cudaFuncSetAttribute(k_spmm_gemm, cudaFuncAttributeMaxDynamicSharedMemorySize, SM_FUSED);

    const int NB_EDGE = (NE + 255) / 256;

    k_count<<<NB_EDGE, 256>>>(src, dst);                         // 0
    k_scanA<<<SCAN_BLOCKS, 256>>>();                             // 1
    k_scanB<<<SCAN_BLOCKS, 256>>>();                             // 2
    k_fill<<<NB_EDGE, 256>>>(src, dst);                          // 3

    // layer 1: embed+spmm+gemm -> hA
    k_l1<<<NB_TILE, 256, SM_L1>>>(nf, Wemb, bemb, Wg, bg, hA);   // 4
    // layer 2: hA -> hB
    k_spmm_gemm<<<NB_TILE, 256, SM_FUSED>>>(hA, Wg + 128 * 128,
                                            bg + 128, hB);       // 5
    // layer 3: hB -> hA
    k_spmm_gemm<<<NB_TILE, 256, SM_FUSED>>>(hB, Wg + 2 * 128 * 128,
                                            bg + 2 * 128, hA);   // 6
    // head: relu(hA@Wo1+b1).Wo2 + b2 -> out
    k_gemm_gemv<<<NB_TILE, 256>>>(hA, Wo1, bo1, Wo2, bo2, out, NN);  // 7
}

// round 5
// speedup vs baseline: 1.3557x; 1.3557x over previous
#include <cuda_runtime.h>
#include <cstdint>

#define NN 50000
#define NE 640000
#define EMB 128
#define SCAN_BLOCKS 196   // 196*256 = 50176 >= NN
#define NB_TILE 391       // (NN+127)/128

// ---- scratch (device globals; zero-initialized at load, re-zeroed each launch) ----
__device__ float g_hA[NN * EMB];      // 25.6 MB
__device__ float g_hB[NN * EMB];      // 25.6 MB
__device__ float g_norm_src[NN];
__device__ float g_norm_dst[NN];
__device__ int   g_deg_src[NN];       // zeroed at end of scanB each launch
__device__ int   g_deg_dst[NN];
__device__ int   g_row_ptr[NN + 1];
__device__ int   g_cursor[NN];
__device__ int   g_col[NE];
__device__ float g_colw[NE];
__device__ int   g_part[SCAN_BLOCKS];

// ---------------------------------------------------------------
__global__ void k_count(const int* __restrict__ src, const int* __restrict__ dst) {
    int e = blockIdx.x * blockDim.x + threadIdx.x;
    if (e < NE) {
        atomicAdd(&g_deg_src[src[e]], 1);
        atomicAdd(&g_deg_dst[dst[e]], 1);
    }
}

__global__ void k_scanA() {
    __shared__ int sh[256];
    int i = blockIdx.x * 256 + threadIdx.x;
    int d = (i < NN) ? g_deg_dst[i] : 0;
    sh[threadIdx.x] = d;
    __syncthreads();
    #pragma unroll
    for (int off = 128; off; off >>= 1) {
        if (threadIdx.x < off) sh[threadIdx.x] += sh[threadIdx.x + off];
        __syncthreads();
    }
    if (threadIdx.x == 0) g_part[blockIdx.x] = sh[0];
}

__global__ void k_scanB() {
    __shared__ int sh[256];
    __shared__ int pre;
    int tid = threadIdx.x;
    int b = blockIdx.x;
    int pv = (tid < b) ? g_part[tid] : 0;
    sh[tid] = pv;
    __syncthreads();
    #pragma unroll
    for (int off = 128; off; off >>= 1) {
        if (tid < off) sh[tid] += sh[tid + off];
        __syncthreads();
    }
    if (tid == 0) pre = sh[0];
    __syncthreads();
    int prefix = pre;
    __syncthreads();

    int i = b * 256 + tid;
    int d = (i < NN) ? g_deg_dst[i] : 0;
    sh[tid] = d;
    __syncthreads();
    #pragma unroll
    for (int off = 1; off < 256; off <<= 1) {
        int v = (tid >= off) ? sh[tid - off] : 0;
        __syncthreads();
        sh[tid] += v;
        __syncthreads();
    }
    int incl = sh[tid];
    int excl = incl - d;
    if (i < NN) {
        int base = prefix + excl;
        g_row_ptr[i] = base;
        g_cursor[i]  = base;
        if (i == NN - 1) g_row_ptr[NN] = prefix + incl;
        int ds = g_deg_src[i];
        g_norm_dst[i] = rsqrtf((float)max(d, 1));
        g_norm_src[i] = rsqrtf((float)max(ds, 1));
        g_deg_dst[i] = 0;
        g_deg_src[i] = 0;
    }
}

__global__ void k_fill(const int* __restrict__ src, const int* __restrict__ dst) {
    int e = blockIdx.x * blockDim.x + threadIdx.x;
    if (e < NE) {
        int s = src[e];
        int pos = atomicAdd(&g_cursor[dst[e]], 1);
        g_col[pos]  = s;
        g_colw[pos] = g_norm_src[s];   // fold src-side norm into edge weight
    }
}

// ---------------------------------------------------------------
// Layer-1 fused aggregate: warp per dst node.
// agg4 = sum_e w*nf4[src], ws = sum_e w  (reduced across lanes)
// out[dst,:] = norm_dst * (agg4 @ W_emb + ws * b_emb)
__global__ void __launch_bounds__(256)
k_spmm_l1(const float* __restrict__ nf, const float* __restrict__ Wemb,
          const float* __restrict__ bemb, float* __restrict__ out) {
    __shared__ float We[512];
    __shared__ float be[128];
    int tid = threadIdx.x;
    if (tid < 256) {
        We[tid] = Wemb[tid];
        We[tid + 256] = Wemb[tid + 256];
        if (tid < 128) be[tid] = bemb[tid];
    }
    __syncthreads();

    int gw = (blockIdx.x * blockDim.x + tid) >> 5;
    int lane = tid & 31;
    if (gw >= NN) return;
    int beg = g_row_ptr[gw];
    int end = g_row_ptr[gw + 1];
    float4 acc = make_float4(0.f, 0.f, 0.f, 0.f);
    float ws = 0.f;
    for (int j = beg + lane; j < end; j += 32) {
        int s = __ldg(&g_col[j]);
        float w = __ldg(&g_colw[j]);
        float4 v = *(const float4*)(nf + (size_t)s * 4);
        acc.x += w * v.x; acc.y += w * v.y;
        acc.z += w * v.z; acc.w += w * v.w;
        ws += w;
    }
    #pragma unroll
    for (int o = 16; o; o >>= 1) {
        acc.x += __shfl_xor_sync(0xffffffffu, acc.x, o);
        acc.y += __shfl_xor_sync(0xffffffffu, acc.y, o);
        acc.z += __shfl_xor_sync(0xffffffffu, acc.z, o);
        acc.w += __shfl_xor_sync(0xffffffffu, acc.w, o);
        ws    += __shfl_xor_sync(0xffffffffu, ws, o);
    }
    float nd = g_norm_dst[gw];
    float4 o4;
    int k = lane * 4;
    o4.x = nd * (acc.x * We[k+0] + acc.y * We[128+k+0] + acc.z * We[256+k+0] + acc.w * We[384+k+0] + ws * be[k+0]);
    o4.y = nd * (acc.x * We[k+1] + acc.y * We[128+k+1] + acc.z * We[256+k+1] + acc.w * We[384+k+1] + ws * be[k+1]);
    o4.z = nd * (acc.x * We[k+2] + acc.y * We[128+k+2] + acc.z * We[256+k+2] + acc.w * We[384+k+2] + ws * be[k+2]);
    o4.w = nd * (acc.x * We[k+3] + acc.y * We[128+k+3] + acc.z * We[256+k+3] + acc.w * We[384+k+3] + ws * be[k+3]);
    *(float4*)(out + (size_t)gw * EMB + k) = o4;
}

// CSR aggregation: one warp per destination node, lane owns 4 floats (float4)
__global__ void k_spmm(const float* __restrict__ h, float* __restrict__ out) {
    int gw = (blockIdx.x * blockDim.x + threadIdx.x) >> 5;
    int lane = threadIdx.x & 31;
    if (gw >= NN) return;
    int beg = g_row_ptr[gw];
    int end = g_row_ptr[gw + 1];
    float4 acc = make_float4(0.f, 0.f, 0.f, 0.f);
    int j = beg;
    for (; j + 4 <= end; j += 4) {
        int   s0 = __ldg(&g_col[j]);
        int   s1 = __ldg(&g_col[j + 1]);
        int   s2 = __ldg(&g_col[j + 2]);
        int   s3 = __ldg(&g_col[j + 3]);
        float w0 = __ldg(&g_colw[j]);
        float w1 = __ldg(&g_colw[j + 1]);
        float w2 = __ldg(&g_colw[j + 2]);
        float w3 = __ldg(&g_colw[j + 3]);
        float4 v0 = *(const float4*)(h + (size_t)s0 * EMB + lane * 4);
        float4 v1 = *(const float4*)(h + (size_t)s1 * EMB + lane * 4);
        float4 v2 = *(const float4*)(h + (size_t)s2 * EMB + lane * 4);
        float4 v3 = *(const float4*)(h + (size_t)s3 * EMB + lane * 4);
        acc.x += w0 * v0.x + w1 * v1.x + w2 * v2.x + w3 * v3.x;
        acc.y += w0 * v0.y + w1 * v1.y + w2 * v2.y + w3 * v3.y;
        acc.z += w0 * v0.z + w1 * v1.z + w2 * v2.z + w3 * v3.z;
        acc.w += w0 * v0.w + w1 * v1.w + w2 * v2.w + w3 * v3.w;
    }
    for (; j < end; j++) {
        int   s0 = __ldg(&g_col[j]);
        float w0 = __ldg(&g_colw[j]);
        float4 v0 = *(const float4*)(h + (size_t)s0 * EMB + lane * 4);
        acc.x += w0 * v0.x;
        acc.y += w0 * v0.y;
        acc.z += w0 * v0.z;
        acc.w += w0 * v0.w;
    }
    float nd = g_norm_dst[gw];
    acc.x *= nd; acc.y *= nd; acc.z *= nd; acc.w *= nd;
    *(float4*)(out + (size_t)gw * EMB + lane * 4) = acc;
}

// ---------------------------------------------------------------
__device__ __forceinline__ uint32_t f2tf32(float f) {
    uint32_t r;
    asm("cvt.rna.tf32.f32 %0, %1;" : "=r"(r) : "f"(f));
    return r;
}

// Tensor-core GEMM: C[M,128] = relu(A[M,128] @ W[128,128] + bias)
// mma.sync.m16n8k8 tf32, fp32 accumulate. 8 warps (4x2), tile 128x128, BK=32.
template <bool RELU>
__global__ void __launch_bounds__(256)
k_gemm_tc(const float* __restrict__ A, const float* __restrict__ W,
          const float* __restrict__ bias, float* __restrict__ C, int M) {
    __shared__ uint32_t As[32][132];
    __shared__ uint32_t Ws[32][132];
    int tid  = threadIdx.x;
    int warp = tid >> 5;
    int lane = tid & 31;
    int wm = warp & 3;
    int wn = warp >> 2;
    int lg = lane >> 2;
    int lt = lane & 3;
    int row0 = blockIdx.x * 128;

    float c[2][8][4] = {};

    for (int k0 = 0; k0 < 128; k0 += 32) {
        #pragma unroll
        for (int it = 0; it < 4; it++) {
            int f  = tid + it * 256;
            int m  = f >> 3;
            int kq = (f & 7) << 2;
            int gr = row0 + m;
            float4 a = (gr < M) ? *(const float4*)(A + (size_t)gr * 128 + k0 + kq)
                                : make_float4(0.f, 0.f, 0.f, 0.f);
            As[kq + 0][m] = f2tf32(a.x);
            As[kq + 1][m] = f2tf32(a.y);
            As[kq + 2][m] = f2tf32(a.z);
            As[kq + 3][m] = f2tf32(a.w);
        }
        #pragma unroll
        for (int it = 0; it < 4; it++) {
            int f = tid + it * 256;
            int k = f >> 5;
            int n = (f & 31) << 2;
            float4 w = *(const float4*)(W + (size_t)(k0 + k) * 128 + n);
            Ws[k][n + 0] = f2tf32(w.x);
            Ws[k][n + 1] = f2tf32(w.y);
            Ws[k][n + 2] = f2tf32(w.z);
            Ws[k][n + 3] = f2tf32(w.w);
        }
        __syncthreads();

        #pragma unroll
        for (int ks = 0; ks < 32; ks += 8) {
            uint32_t af[2][4];
            #pragma unroll
            for (int mt = 0; mt < 2; mt++) {
                int m = wm * 32 + mt * 16 + lg;
                af[mt][0] = As[ks + lt][m];
                af[mt][1] = As[ks + lt][m + 8];
                af[mt][2] = As[ks + 4 + lt][m];
                af[mt][3] = As[ks + 4 + lt][m + 8];
            }
            #pragma unroll
            for (int nt = 0; nt < 8; nt++) {
                int n = wn * 64 + nt * 8 + lg;
                uint32_t b0 = Ws[ks + lt][n];
                uint32_t b1 = Ws[ks + 4 + lt][n];
                #pragma unroll
                for (int mt = 0; mt < 2; mt++) {
                    asm volatile(
                        "mma.sync.aligned.m16n8k8.row.col.f32.tf32.tf32.f32 "
                        "{%0,%1,%2,%3}, {%4,%5,%6,%7}, {%8,%9}, {%0,%1,%2,%3};"
                        : "+f"(c[mt][nt][0]), "+f"(c[mt][nt][1]),
                          "+f"(c[mt][nt][2]), "+f"(c[mt][nt][3])
                        : "r"(af[mt][0]), "r"(af[mt][1]),
                          "r"(af[mt][2]), "r"(af[mt][3]),
                          "r"(b0), "r"(b1));
                }
            }
        }
        __syncthreads();
    }

    #pragma unroll
    for (int nt = 0; nt < 8; nt++) {
        int col = wn * 64 + nt * 8 + 2 * lt;
        float2 bv = *(const float2*)(bias + col);
        #pragma unroll
        for (int mt = 0; mt < 2; mt++) {
            int r = row0 + wm * 32 + mt * 16 + lg;
            float2 o0, o1;
            o0.x = c[mt][nt][0] + bv.x;
            o0.y = c[mt][nt][1] + bv.y;
            o1.x = c[mt][nt][2] + bv.x;
            o1.y = c[mt][nt][3] + bv.y;
            if (RELU) {
                o0.x = fmaxf(o0.x, 0.f); o0.y = fmaxf(o0.y, 0.f);
                o1.x = fmaxf(o1.x, 0.f); o1.y = fmaxf(o1.y, 0.f);
            }
            if (r < M)     *(float2*)(C + (size_t)r * 128 + col)       = o0;
            if (r + 8 < M) *(float2*)(C + (size_t)(r + 8) * 128 + col) = o1;
        }
    }
}

// ---------------------------------------------------------------
// Final fused: out[r] = relu(A[r,:] @ Wo1 + b1) . w2 + b2
__global__ void __launch_bounds__(256)
k_gemm_gemv(const float* __restrict__ A, const float* __restrict__ W,
            const float* __restrict__ bias, const float* __restrict__ w2,
            const float* __restrict__ b2, float* __restrict__ out, int M) {
    __shared__ uint32_t As[32][132];
    __shared__ uint32_t Ws[32][132];
    __shared__ float red[128];
    __shared__ float w2s[128];
    int tid  = threadIdx.x;
    int warp = tid >> 5, lane = tid & 31;
    int wm = warp & 3, wn = warp >> 2;
    int lg = lane >> 2, lt = lane & 3;
    int row0 = blockIdx.x * 128;

    if (tid < 128) { red[tid] = 0.f; w2s[tid] = w2[tid]; }

    float c[2][8][4] = {};

    for (int k0 = 0; k0 < 128; k0 += 32) {
        #pragma unroll
        for (int it = 0; it < 4; it++) {
            int f  = tid + it * 256;
            int m  = f >> 3;
            int kq = (f & 7) << 2;
            int gr = row0 + m;
            float4 a = (gr < M) ? *(const float4*)(A + (size_t)gr * 128 + k0 + kq)
                                : make_float4(0.f, 0.f, 0.f, 0.f);
            As[kq + 0][m] = f2tf32(a.x);
            As[kq + 1][m] = f2tf32(a.y);
            As[kq + 2][m] = f2tf32(a.z);
            As[kq + 3][m] = f2tf32(a.w);
        }
        #pragma unroll
        for (int it = 0; it < 4; it++) {
            int f = tid + it * 256;
            int k = f >> 5;
            int n = (f & 31) << 2;
            float4 w = *(const float4*)(W + (size_t)(k0 + k) * 128 + n);
            Ws[k][n + 0] = f2tf32(w.x);
            Ws[k][n + 1] = f2tf32(w.y);
            Ws[k][n + 2] = f2tf32(w.z);
            Ws[k][n + 3] = f2tf32(w.w);
        }
        __syncthreads();

        #pragma unroll
        for (int ks = 0; ks < 32; ks += 8) {
            uint32_t af[2][4];
            #pragma unroll
            for (int mt = 0; mt < 2; mt++) {
                int m = wm * 32 + mt * 16 + lg;
                af[mt][0] = As[ks + lt][m];
                af[mt][1] = As[ks + lt][m + 8];
                af[mt][2] = As[ks + 4 + lt][m];
                af[mt][3] = As[ks + 4 + lt][m + 8];
            }
            #pragma unroll
            for (int nt = 0; nt < 8; nt++) {
                int n = wn * 64 + nt * 8 + lg;
                uint32_t b0 = Ws[ks + lt][n];
                uint32_t b1 = Ws[ks + 4 + lt][n];
                #pragma unroll
                for (int mt = 0; mt < 2; mt++) {
                    asm volatile(
                        "mma.sync.aligned.m16n8k8.row.col.f32.tf32.tf32.f32 "
                        "{%0,%1,%2,%3}, {%4,%5,%6,%7}, {%8,%9}, {%0,%1,%2,%3};"
                        : "+f"(c[mt][nt][0]), "+f"(c[mt][nt][1]),
                          "+f"(c[mt][nt][2]), "+f"(c[mt][nt][3])
                        : "r"(af[mt][0]), "r"(af[mt][1]),
                          "r"(af[mt][2]), "r"(af[mt][3]),
                          "r"(b0), "r"(b1));
                }
            }
        }
        __syncthreads();
    }

    #pragma unroll
    for (int mt = 0; mt < 2; mt++) {
        float dot0 = 0.f, dot1 = 0.f;
        #pragma unroll
        for (int nt = 0; nt < 8; nt++) {
            int col = wn * 64 + nt * 8 + 2 * lt;
            float2 bv = *(const float2*)(bias + col);
            float wa = w2s[col], wb = w2s[col + 1];
            dot0 += fmaxf(c[mt][nt][0] + bv.x, 0.f) * wa
                  + fmaxf(c[mt][nt][1] + bv.y, 0.f) * wb;
            dot1 += fmaxf(c[mt][nt][2] + bv.x, 0.f) * wa
                  + fmaxf(c[mt][nt][3] + bv.y, 0.f) * wb;
        }
        int rl = wm * 32 + mt * 16 + lg;
        atomicAdd(&red[rl], dot0);
        atomicAdd(&red[rl + 8], dot1);
    }
    __syncthreads();
    if (tid < 128 && row0 + tid < M)
        out[row0 + tid] = red[tid] + b2[0];
}

// ---------------------------------------------------------------
extern "C" void kernel_launch(void* const* d_in, const int* in_sizes, int n_in,
                              void* d_out, int out_size) {
    const float* nf   = (const float*)d_in[0];
    const int*   src  = (const int*)d_in[1];
    const int*   dst  = (const int*)d_in[2];
    const float* Wemb = (const float*)d_in[3];
    const float* bemb = (const float*)d_in[4];
    const float* Wg   = (const float*)d_in[5];
    const float* bg   = (const float*)d_in[6];
    const float* Wo1  = (const float*)d_in[7];
    const float* bo1  = (const float*)d_in[8];
    const float* Wo2  = (const float*)d_in[9];
    const float* bo2  = (const float*)d_in[10];
    float* out = (float*)d_out;

    float *hA, *hB;
    cudaGetSymbolAddress((void**)&hA, g_hA);
    cudaGetSymbolAddress((void**)&hB, g_hB);

    const int NB_EDGE = (NE + 255) / 256;
    const int NB_WARP = (NN * 32 + 255) / 256;   // warp-per-node kernels

    k_count<<<NB_EDGE, 256>>>(src, dst);                        // 0
    k_scanA<<<SCAN_BLOCKS, 256>>>();                            // 1
    k_scanB<<<SCAN_BLOCKS, 256>>>();                            // 2
    k_fill<<<NB_EDGE, 256>>>(src, dst);                         // 3

    // layer 1: fused embed+aggregate -> hB, then GEMM -> hA
    k_spmm_l1<<<NB_WARP, 256>>>(nf, Wemb, bemb, hB);            // 4
    k_gemm_tc<true><<<NB_TILE, 256>>>(hB, Wg, bg, hA, NN);      // 5

    // layers 2,3
    k_spmm<<<NB_WARP, 256>>>(hA, hB);                           // 6
    k_gemm_tc<true><<<NB_TILE, 256>>>(hB, Wg + 128 * 128,
                                      bg + 128, hA, NN);        // 7
    k_spmm<<<NB_WARP, 256>>>(hA, hB);                           // 8
    k_gemm_tc<true><<<NB_TILE, 256>>>(hB, Wg + 2 * 128 * 128,
                                      bg + 2 * 128, hA, NN);    // 9

    // head: relu(hA@Wo1+b1).Wo2 + b2 -> out
    k_gemm_gemv<<<NB_TILE, 256>>>(hA, Wo1, bo1, Wo2, bo2, out, NN);  // 10
}